// round 4
// baseline (speedup 1.0000x reference)
#include <cuda_runtime.h>
#include <cstdint>
#include <cstddef>

// Problem constants
#define LNUM 3
#define HDIM 128
#define NHEADS 8
#define HD 16
#define FF 512
#define BSZ 32
#define NN 512
#define ROWS (BSZ*NN)          // 16384
#define NUM_BINS 50
#define KS 17                  // padded smem stride for K/V tiles

// -------------------- scratch (device globals; no allocation) --------------------
__device__ float g_t0[ROWS*HDIM];
__device__ float g_q [ROWS*HDIM];
__device__ float g_k [ROWS*HDIM];
__device__ float g_v [ROWS*HDIM];
__device__ float g_a [ROWS*HDIM];
__device__ float g_u [ROWS*2*FF];
__device__ float g_g [ROWS*FF];

// -------------------- LayerNorm: one warp per 128-elem row --------------------
__global__ void ln_kernel(const float* __restrict__ x, const float* __restrict__ g,
                          const float* __restrict__ b, float* __restrict__ y)
{
    int warp = threadIdx.x >> 5, lane = threadIdx.x & 31;
    int row  = blockIdx.x * 8 + warp;
    const float4* x4 = (const float4*)(x + (size_t)row * HDIM);
    float4 v = x4[lane];
    float s  = v.x + v.y + v.z + v.w;
    float sq = v.x*v.x + v.y*v.y + v.z*v.z + v.w*v.w;
    #pragma unroll
    for (int o = 16; o > 0; o >>= 1) {
        s  += __shfl_xor_sync(0xffffffffu, s,  o);
        sq += __shfl_xor_sync(0xffffffffu, sq, o);
    }
    float mu  = s * (1.0f/128.0f);
    float var = sq * (1.0f/128.0f) - mu*mu;
    float rs  = rsqrtf(var + 1e-5f);
    float4 gg = ((const float4*)g)[lane];
    float4 bb = ((const float4*)b)[lane];
    float4 o;
    o.x = (v.x - mu) * rs * gg.x + bb.x;
    o.y = (v.y - mu) * rs * gg.y + bb.y;
    o.z = (v.z - mu) * rs * gg.z + bb.z;
    o.w = (v.w - mu) * rs * gg.w + bb.w;
    ((float4*)(y + (size_t)row * HDIM))[lane] = o;
}

// -------------------- tiled fp32 GEMM: C = [C +] A[M,K] @ W[K,N] + bias --------------------
template<bool ADD>
__global__ __launch_bounds__(256)
void gemm64(const float* __restrict__ A, const float* __restrict__ W,
            const float* __restrict__ bias, float* __restrict__ C,
            int M, int N, int K)
{
    __shared__ float As[16][65];
    __shared__ float Ws[16][64];
    int tid = threadIdx.x;
    int tx = tid & 15, ty = tid >> 4;
    int m0 = blockIdx.y * 64, n0 = blockIdx.x * 64;

    int lr = tid >> 2, lc = tid & 3;    // A tile load: row, float4-col
    int wk = tid >> 4, wc = tid & 15;   // W tile load: k-row, float4-col

    float acc[4][4];
    #pragma unroll
    for (int i = 0; i < 4; i++)
        #pragma unroll
        for (int j = 0; j < 4; j++) acc[i][j] = 0.0f;

    for (int k0 = 0; k0 < K; k0 += 16) {
        float4 av = *(const float4*)(A + (size_t)(m0 + lr) * K + k0 + lc * 4);
        As[lc*4+0][lr] = av.x; As[lc*4+1][lr] = av.y;
        As[lc*4+2][lr] = av.z; As[lc*4+3][lr] = av.w;
        float4 wv = *(const float4*)(W + (size_t)(k0 + wk) * N + n0 + wc * 4);
        *(float4*)&Ws[wk][wc*4] = wv;
        __syncthreads();
        #pragma unroll
        for (int k = 0; k < 16; k++) {
            float a[4];
            #pragma unroll
            for (int i = 0; i < 4; i++) a[i] = As[k][ty*4 + i];
            float4 bv = *(float4*)&Ws[k][tx*4];
            float bb[4] = {bv.x, bv.y, bv.z, bv.w};
            #pragma unroll
            for (int i = 0; i < 4; i++)
                #pragma unroll
                for (int j = 0; j < 4; j++)
                    acc[i][j] = fmaf(a[i], bb[j], acc[i][j]);
        }
        __syncthreads();
    }

    float4 bvec = *(const float4*)(bias + n0 + tx*4);
    float bs[4] = {bvec.x, bvec.y, bvec.z, bvec.w};
    #pragma unroll
    for (int i = 0; i < 4; i++) {
        size_t off = (size_t)(m0 + ty*4 + i) * N + n0 + tx*4;
        float4 o;
        o.x = acc[i][0] + bs[0];
        o.y = acc[i][1] + bs[1];
        o.z = acc[i][2] + bs[2];
        o.w = acc[i][3] + bs[3];
        if (ADD) {
            float4 r = *(const float4*)(C + off);
            o.x += r.x; o.y += r.y; o.z += r.z; o.w += r.w;
        }
        *(float4*)(C + off) = o;
    }
}

// -------------------- fused attention: warp per query row, full K/V for (b,h) in smem --------------------
__global__ __launch_bounds__(512, 1)
void attn_kernel(const float* __restrict__ Q, const float* __restrict__ Kt,
                 const float* __restrict__ V, const float* __restrict__ dist,
                 const unsigned int* __restrict__ mask,   // 4-byte elements; nonzero bits = masked
                 const float* __restrict__ demb,   // [50,8] for this layer
                 const float* __restrict__ abias,  // [8]    for this layer
                 float* __restrict__ out)
{
    extern __shared__ float sm[];
    float* Ksh = sm;                 // 512*17
    float* Vsh = Ksh + NN*KS;        // 512*17
    float* mb  = Vsh + NN*KS;        // 512
    float* de  = mb + NN;            // 64

    int b = blockIdx.x >> 3, h = blockIdx.x & 7;
    int tid = threadIdx.x;

    // cooperative load of K,V head slice [512,16] into padded smem
    for (int idx = tid; idx < NN*4; idx += 512) {
        int r = idx >> 2, c = idx & 3;
        size_t goff = ((size_t)b*NN + r) * HDIM + h*HD + c*4;
        float4 kv = *(const float4*)(Kt + goff);
        Ksh[r*KS + c*4+0] = kv.x; Ksh[r*KS + c*4+1] = kv.y;
        Ksh[r*KS + c*4+2] = kv.z; Ksh[r*KS + c*4+3] = kv.w;
        float4 vv = *(const float4*)(V + goff);
        Vsh[r*KS + c*4+0] = vv.x; Vsh[r*KS + c*4+1] = vv.y;
        Vsh[r*KS + c*4+2] = vv.z; Vsh[r*KS + c*4+3] = vv.w;
    }
    // mask element i is a 4-byte word (int32 `1`/`0` or float32 `1.0f`/`0.0f`):
    // nonzero bit pattern <=> masked. Works for both encodings.
    if (tid < NN)  mb[tid] = (mask[(size_t)b*NN + tid] != 0u) ? -1e9f : 0.0f;
    if (tid < NUM_BINS) de[tid] = demb[tid*NHEADS + h];
    float ab = abias[h];
    __syncthreads();

    int warp = tid >> 5, lane = tid & 31;
    int qbase = blockIdx.y * 64 + warp * 4;

    for (int r = 0; r < 4; r++) {
        int q = qbase + r;
        const float* qp = Q + ((size_t)b*NN + q) * HDIM + h*HD;
        float qv[HD];
        #pragma unroll
        for (int d = 0; d < HD; d++) qv[d] = __ldg(qp + d);

        const float* drow = dist + ((size_t)b*NN + q) * NN;
        float sc[16];
        float mx = -3.4e38f;
        #pragma unroll
        for (int kk = 0; kk < 16; kk++) {
            int k = kk*32 + lane;
            float dv = drow[k];                       // coalesced across lanes
            int bin = (int)(dv * 10.0f);
            bin = bin < 0 ? 0 : (bin > NUM_BINS-1 ? NUM_BINS-1 : bin);
            float dot = 0.0f;
            #pragma unroll
            for (int d = 0; d < HD; d++) dot = fmaf(qv[d], Ksh[k*KS + d], dot);
            float s = dot * 0.25f + de[bin] + ab + mb[k];
            sc[kk] = s;
            mx = fmaxf(mx, s);
        }
        #pragma unroll
        for (int o = 16; o > 0; o >>= 1)
            mx = fmaxf(mx, __shfl_xor_sync(0xffffffffu, mx, o));

        float ssum = 0.0f, acc[HD];
        #pragma unroll
        for (int d = 0; d < HD; d++) acc[d] = 0.0f;
        #pragma unroll
        for (int kk = 0; kk < 16; kk++) {
            int k = kk*32 + lane;
            float p = __expf(fmaxf(sc[kk] - mx, -80.0f));
            ssum += p;
            #pragma unroll
            for (int d = 0; d < HD; d++)
                acc[d] = fmaf(p, Vsh[k*KS + d], acc[d]);
        }
        #pragma unroll
        for (int o = 16; o > 0; o >>= 1) {
            ssum += __shfl_xor_sync(0xffffffffu, ssum, o);
            #pragma unroll
            for (int d = 0; d < HD; d++)
                acc[d] += __shfl_xor_sync(0xffffffffu, acc[d], o);
        }
        if (lane == 0) {
            float inv = 1.0f / ssum;
            float4* o4 = (float4*)(out + ((size_t)b*NN + q) * HDIM + h*HD);
            o4[0] = make_float4(acc[0]*inv,  acc[1]*inv,  acc[2]*inv,  acc[3]*inv);
            o4[1] = make_float4(acc[4]*inv,  acc[5]*inv,  acc[6]*inv,  acc[7]*inv);
            o4[2] = make_float4(acc[8]*inv,  acc[9]*inv,  acc[10]*inv, acc[11]*inv);
            o4[3] = make_float4(acc[12]*inv, acc[13]*inv, acc[14]*inv, acc[15]*inv);
        }
    }
}

// -------------------- GLU: g = u[:, :FF] * sigmoid(u[:, FF:]) --------------------
__global__ void glu_kernel(const float* __restrict__ u, float* __restrict__ g, int total4)
{
    int idx = blockIdx.x * blockDim.x + threadIdx.x;
    if (idx >= total4) return;
    int r = idx >> 7, j4 = idx & 127;
    float4 a = *(const float4*)(u + (size_t)r * (2*FF) + j4*4);
    float4 c = *(const float4*)(u + (size_t)r * (2*FF) + FF + j4*4);
    float4 o;
    o.x = a.x / (1.0f + __expf(-c.x));
    o.y = a.y / (1.0f + __expf(-c.y));
    o.z = a.z / (1.0f + __expf(-c.z));
    o.w = a.w / (1.0f + __expf(-c.w));
    *(float4*)(g + (size_t)r * FF + j4*4) = o;
}

// -------------------- launch --------------------
extern "C" void kernel_launch(void* const* d_in, const int* in_sizes, int n_in,
                              void* d_out, int out_size)
{
    const float*        x    = (const float*)d_in[0];
    const float*        dist = (const float*)d_in[1];
    const unsigned int* mask = (const unsigned int*)d_in[2];  // bool widened to 4-byte dtype
    const float* Wq  = (const float*)d_in[3];
    const float* bq  = (const float*)d_in[4];
    const float* Wk  = (const float*)d_in[5];
    const float* bk  = (const float*)d_in[6];
    const float* Wv  = (const float*)d_in[7];
    const float* bv  = (const float*)d_in[8];
    const float* Wo  = (const float*)d_in[9];
    const float* bo  = (const float*)d_in[10];
    const float* demb  = (const float*)d_in[11];
    const float* abias = (const float*)d_in[12];
    const float* g1  = (const float*)d_in[13];
    const float* b1  = (const float*)d_in[14];
    const float* g2  = (const float*)d_in[15];
    const float* b2  = (const float*)d_in[16];
    const float* Wf1 = (const float*)d_in[17];
    const float* bf1 = (const float*)d_in[18];
    const float* Wf2 = (const float*)d_in[19];
    const float* bf2 = (const float*)d_in[20];
    float* h = (float*)d_out;

    float *t0, *q, *k, *v, *a, *u, *g;
    cudaGetSymbolAddress((void**)&t0, g_t0);
    cudaGetSymbolAddress((void**)&q,  g_q);
    cudaGetSymbolAddress((void**)&k,  g_k);
    cudaGetSymbolAddress((void**)&v,  g_v);
    cudaGetSymbolAddress((void**)&a,  g_a);
    cudaGetSymbolAddress((void**)&u,  g_u);
    cudaGetSymbolAddress((void**)&g,  g_g);

    const int SMEM = (2*NN*KS + NN + 64) * (int)sizeof(float);
    cudaFuncSetAttribute(attn_kernel, cudaFuncAttributeMaxDynamicSharedMemorySize, SMEM);

    cudaMemcpyAsync(h, x, sizeof(float)*(size_t)ROWS*HDIM, cudaMemcpyDeviceToDevice, 0);

    for (int l = 0; l < LNUM; l++) {
        ln_kernel<<<ROWS/8, 256>>>(h, g1 + l*HDIM, b1 + l*HDIM, t0);

        gemm64<false><<<dim3(HDIM/64, ROWS/64), 256>>>(t0, Wq + (size_t)l*HDIM*HDIM, bq + l*HDIM, q, ROWS, HDIM, HDIM);
        gemm64<false><<<dim3(HDIM/64, ROWS/64), 256>>>(t0, Wk + (size_t)l*HDIM*HDIM, bk + l*HDIM, k, ROWS, HDIM, HDIM);
        gemm64<false><<<dim3(HDIM/64, ROWS/64), 256>>>(t0, Wv + (size_t)l*HDIM*HDIM, bv + l*HDIM, v, ROWS, HDIM, HDIM);

        attn_kernel<<<dim3(BSZ*NHEADS, NN/64), 512, SMEM>>>(q, k, v, dist, mask,
                                                            demb + l*NUM_BINS*NHEADS,
                                                            abias + l*NHEADS, a);

        gemm64<true><<<dim3(HDIM/64, ROWS/64), 256>>>(a, Wo + (size_t)l*HDIM*HDIM, bo + l*HDIM, h, ROWS, HDIM, HDIM);

        ln_kernel<<<ROWS/8, 256>>>(h, g2 + l*HDIM, b2 + l*HDIM, t0);

        gemm64<false><<<dim3((2*FF)/64, ROWS/64), 256>>>(t0, Wf1 + (size_t)l*HDIM*2*FF, bf1 + l*2*FF, u, ROWS, 2*FF, HDIM);

        glu_kernel<<<(ROWS*FF/4 + 255)/256, 256>>>(u, g, ROWS*FF/4);

        gemm64<true><<<dim3(HDIM/64, ROWS/64), 256>>>(g, Wf2 + (size_t)l*FF*HDIM, bf2 + l*HDIM, h, ROWS, HDIM, FF);
    }
}